// round 1
// baseline (speedup 1.0000x reference)
#include <cuda_runtime.h>
#include <math.h>

#define Dk 512
#define Ek 8
#define Hk 128
#define MAXN 32768
#define CAPSTRIDE 5120
#define NBMAX (MAXN/256)

// ---------------- device scratch (no allocations allowed) ----------------
__device__ int   g_top[MAXN];          // packed top-2 expert ids per token
__device__ float g_conf[MAXN];         // top-1 logit per token
__device__ int   g_bcnt[NBMAX*Ek];     // per-block per-expert routed counts
__device__ int   g_boff[NBMAX*Ek];     // exclusive prefix of the above
__device__ float g_csum[NBMAX];        // per-block confidence partial sums
__device__ int   g_list[Ek*CAPSTRIDE]; // compacted kept-token lists
__device__ int   g_Me[Ek];             // kept count per expert (= load)

// ---------------- router: logits = x@Wr + br, top-2, confidence ----------
__global__ void router_kernel(const float* __restrict__ x,
                              const float* __restrict__ Wr,
                              const float* __restrict__ br, int N)
{
    __shared__ float sWr[Dk*Ek]; // 16 KB
    int t = threadIdx.x;
    for (int i = t; i < Dk*Ek/4; i += 256)
        ((float4*)sWr)[i] = ((const float4*)Wr)[i];
    __syncthreads();

    int tok  = blockIdx.x*8 + (t >> 5);   // one warp per token
    int lane = t & 31;
    if (tok >= N) return;
    const float* xr = x + (size_t)tok*Dk;

    float acc[Ek];
#pragma unroll
    for (int e = 0; e < Ek; e++) acc[e] = 0.f;

    for (int c = lane; c < Dk/4; c += 32) {
        float4 v = *(const float4*)(xr + c*4);
        const float* w = sWr + c*4*Ek;
        float xv[4] = {v.x, v.y, v.z, v.w};
#pragma unroll
        for (int kk = 0; kk < 4; kk++)
#pragma unroll
            for (int e = 0; e < Ek; e++)
                acc[e] = fmaf(xv[kk], w[kk*Ek + e], acc[e]);
    }
#pragma unroll
    for (int off = 16; off; off >>= 1)
#pragma unroll
        for (int e = 0; e < Ek; e++)
            acc[e] += __shfl_xor_sync(0xffffffffu, acc[e], off);

    if (lane == 0) {
        float v1 = -3e38f, v2 = -3e38f; int i1 = 0, i2 = 1;
#pragma unroll
        for (int e = 0; e < Ek; e++) {
            float v = acc[e] + br[e];
            if (v > v1)      { v2 = v1; i2 = i1; v1 = v; i1 = e; }  // strict > matches jax tie order
            else if (v > v2) { v2 = v;  i2 = e; }
        }
        g_top[tok]  = i1 | (i2 << 4);
        g_conf[tok] = v1;
    }
}

// ---------------- scan stage 1: per-block routed counts + conf partials --
__global__ void scan1_kernel(int N)
{
    __shared__ int   cnt[Ek];
    __shared__ float red[256];
    int t = threadIdx.x, b = blockIdx.x;
    if (t < Ek) cnt[t] = 0;
    __syncthreads();
    int n = b*256 + t;
    float c = 0.f;
    if (n < N) {
        int pk = g_top[n];
        atomicAdd(&cnt[pk & 15], 1);
        atomicAdd(&cnt[(pk >> 4) & 15], 1);
        c = g_conf[n];
    }
    red[t] = c; __syncthreads();
    for (int s = 128; s > 0; s >>= 1) { if (t < s) red[t] += red[t+s]; __syncthreads(); }
    if (t < Ek) g_bcnt[b*Ek + t] = cnt[t];
    if (t == 0) g_csum[b] = red[0];
}

// ---------------- scan stage 2: exclusive scan + load stats + tail out ---
__global__ void scan2_kernel(int NB, int N, int cap, float* tail)
{
    int e = threadIdx.x;
    __shared__ int totals[Ek];
    if (e < Ek) {
        int run = 0;
        for (int b = 0; b < NB; b++) { g_boff[b*Ek + e] = run; run += g_bcnt[b*Ek + e]; }
        totals[e] = run;
        g_Me[e] = run < cap ? run : cap;
    }
    __syncthreads();
    if (e == 0) {
        float s = 0.f, load[Ek];
        for (int i = 0; i < Ek; i++) {
            int l = totals[i] < cap ? totals[i] : cap;
            load[i] = (float)l; s += load[i];
        }
        float inv = 1.f / (s + 1e-8f);
        float loss = 0.f;
        for (int i = 0; i < Ek; i++) {
            float d = load[i] * inv;
            loss += d * logf(d + 1e-8f);
            tail[1 + i] = d;               // load_dist
        }
        tail[0] = loss;                    // load_loss
        float cs = 0.f;
        for (int b = 0; b < NB; b++) cs += g_csum[b];
        tail[9] = cs / (float)N;           // confidence
    }
}

// ---------------- scan stage 3: build compacted kept-token lists ---------
__global__ void scan3_kernel(int N, int cap)
{
    int e = threadIdx.x;
    if (e >= Ek) return;
    int b = blockIdx.x;
    int base = b*256;
    int run = g_boff[b*Ek + e];
    int lim = N - base; if (lim > 256) lim = 256;
    for (int i = 0; i < lim; i++) {
        int pk = g_top[base + i];
        if ((pk & 15) == e || ((pk >> 4) & 15) == e) {
            if (run < cap) g_list[e*CAPSTRIDE + run] = base + i;
            run++;
        }
    }
}

// ---------------- fused per-expert FFN: out += relu(Xg W1 + b1) W2 + b2 --
// block = 256 threads (16x16), tile: MT=64 tokens x full H=128, fp32 SIMT
__global__ void __launch_bounds__(256)
ffn_kernel(const float* __restrict__ x,  const float* __restrict__ W1,
           const float* __restrict__ b1, const float* __restrict__ W2,
           const float* __restrict__ b2, float* __restrict__ out)
{
    constexpr int MT = 64, KT = 16, HS = 129; // HS pad kills bank conflicts on Hs reads
    __shared__ float Xs[KT*MT];     //  4 KB (k-major)
    __shared__ float Ws[KT*Hk];     //  8 KB (shared by both GEMM phases)
    __shared__ float Hs[MT*HS];     // ~33 KB
    __shared__ int   rows[MT];

    int e  = blockIdx.y;
    int Me = g_Me[e];
    int m0 = blockIdx.x * MT;
    if (m0 >= Me) return;

    int tid = threadIdx.x;
    int tx = tid & 15, ty = tid >> 4;

    if (tid < MT) {
        int m = m0 + tid;
        rows[tid] = g_list[e*CAPSTRIDE + (m < Me ? m : (Me - 1))];
    }
    __syncthreads();

    // ---- phase 1: H[64,128] = Xg[64,512] @ W1[512,128] ----
    const float* W1e = W1 + (size_t)e*Dk*Hk;
    float acc[4][8];
#pragma unroll
    for (int i = 0; i < 4; i++)
#pragma unroll
        for (int j = 0; j < 8; j++) acc[i][j] = 0.f;

    for (int k0 = 0; k0 < Dk; k0 += KT) {
        { // gather X tile -> Xs[k][m] (transposed)
            int m = tid >> 2, c4 = tid & 3;
            float4 v = *(const float4*)(x + (size_t)rows[m]*Dk + k0 + c4*4);
            Xs[(c4*4+0)*MT + m] = v.x; Xs[(c4*4+1)*MT + m] = v.y;
            Xs[(c4*4+2)*MT + m] = v.z; Xs[(c4*4+3)*MT + m] = v.w;
        }
#pragma unroll
        for (int r = 0; r < 2; r++) { // W1 tile -> Ws[k][h]
            int q = tid*2 + r; int k = q >> 5; int h = (q & 31)*4;
            *(float4*)&Ws[k*Hk + h] = *(const float4*)&W1e[(size_t)(k0+k)*Hk + h];
        }
        __syncthreads();
#pragma unroll
        for (int k = 0; k < KT; k++) {
            float a[4], bfr[8];
            *(float4*)&a[0]   = *(const float4*)&Xs[k*MT + ty*4];
            *(float4*)&bfr[0] = *(const float4*)&Ws[k*Hk + tx*8];
            *(float4*)&bfr[4] = *(const float4*)&Ws[k*Hk + tx*8 + 4];
#pragma unroll
            for (int i = 0; i < 4; i++)
#pragma unroll
                for (int j = 0; j < 8; j++)
                    acc[i][j] = fmaf(a[i], bfr[j], acc[i][j]);
        }
        __syncthreads();
    }

    // ---- relu + b1 -> Hs[m][h] ----
    {
        const float* b1e = b1 + e*Hk;
        float bb[8];
#pragma unroll
        for (int j = 0; j < 8; j++) bb[j] = b1e[tx*8 + j];
#pragma unroll
        for (int i = 0; i < 4; i++)
#pragma unroll
            for (int j = 0; j < 8; j++)
                Hs[(ty*4+i)*HS + tx*8 + j] = fmaxf(acc[i][j] + bb[j], 0.f);
    }
    __syncthreads();

    // ---- phase 2: out[64,512] += H[64,128] @ W2[128,512] + b2 ----
    const float* W2e = W2 + (size_t)e*Hk*Dk;
    const float* b2e = b2 + (size_t)e*Dk;
    for (int n0 = 0; n0 < Dk; n0 += 128) {
        float acc2[4][8];
#pragma unroll
        for (int i = 0; i < 4; i++)
#pragma unroll
            for (int j = 0; j < 8; j++) acc2[i][j] = 0.f;

        for (int k0 = 0; k0 < Hk; k0 += KT) {
#pragma unroll
            for (int r = 0; r < 2; r++) { // W2 chunk -> Ws[k][h]
                int q = tid*2 + r; int k = q >> 5; int h = (q & 31)*4;
                *(float4*)&Ws[k*Hk + h] = *(const float4*)&W2e[(size_t)(k0+k)*Dk + n0 + h];
            }
            __syncthreads();
#pragma unroll
            for (int k = 0; k < KT; k++) {
                float bfr[8];
                *(float4*)&bfr[0] = *(const float4*)&Ws[k*Hk + tx*8];
                *(float4*)&bfr[4] = *(const float4*)&Ws[k*Hk + tx*8 + 4];
#pragma unroll
                for (int i = 0; i < 4; i++) {
                    float a = Hs[(ty*4+i)*HS + k0 + k];
#pragma unroll
                    for (int j = 0; j < 8; j++)
                        acc2[i][j] = fmaf(a, bfr[j], acc2[i][j]);
                }
            }
            __syncthreads();
        }

        float b2r[8];
#pragma unroll
        for (int j = 0; j < 8; j++) b2r[j] = b2e[n0 + tx*8 + j];
#pragma unroll
        for (int i = 0; i < 4; i++) {
            if (m0 + ty*4 + i < Me) {
                float* op = out + (size_t)rows[ty*4+i]*Dk + n0 + tx*8;
#pragma unroll
                for (int j = 0; j < 8; j++)
                    atomicAdd(op + j, acc2[i][j] + b2r[j]);
            }
        }
    }
}

// ---------------- launch ----------------
extern "C" void kernel_launch(void* const* d_in, const int* in_sizes, int n_in,
                              void* d_out, int out_size)
{
    const float* x  = (const float*)d_in[0];
    const float* Wr = (const float*)d_in[1];
    const float* br = (const float*)d_in[2];
    const float* W1 = (const float*)d_in[3];
    const float* b1 = (const float*)d_in[4];
    const float* W2 = (const float*)d_in[5];
    const float* b2 = (const float*)d_in[6];
    float* out = (float*)d_out;

    int N = in_sizes[0] / Dk;
    if (N > MAXN) N = MAXN;
    int cap = (int)(1.25f * ((float)N / (float)Ek));
    if (cap > CAPSTRIDE) cap = CAPSTRIDE;
    int NB = (N + 255) / 256;

    cudaMemsetAsync(d_out, 0, (size_t)out_size * sizeof(float), 0);
    router_kernel<<<(N + 7) / 8, 256>>>(x, Wr, br, N);
    scan1_kernel<<<NB, 256>>>(N);
    scan2_kernel<<<1, Ek>>>(NB, N, cap, out + (size_t)N * Dk);
    scan3_kernel<<<NB, 32>>>(N, cap);

    int tiles = (cap + 63) / 64;
    dim3 grid(tiles, Ek);
    ffn_kernel<<<grid, 256>>>(x, W1, b1, W2, b2, out);
}

// round 2
// speedup vs baseline: 1.0293x; 1.0293x over previous
#include <cuda_runtime.h>
#include <math.h>

#define Dk 512
#define Ek 8
#define Hk 128
#define MAXN 32768
#define CAPSTRIDE 5120
#define NBMAX (MAXN/256)

typedef unsigned long long ull;

// pack a float into both halves of a 64-bit f32x2 register
#define PACK2(d, v) do { unsigned _u = __float_as_uint(v); \
    asm("mov.b64 %0, {%1, %2};" : "=l"(d) : "r"(_u), "r"(_u)); } while(0)
// d = a * b + d   (elementwise on f32x2 pairs)  — FFMA2 in SASS
#define FMA2(d, a, b) asm("fma.rn.f32x2 %0, %1, %2, %0;" : "+l"(d) : "l"(a), "l"(b))
#define UNPACK2(lo, hi, d) do { unsigned _l, _h; \
    asm("mov.b64 {%0, %1}, %2;" : "=r"(_l), "=r"(_h) : "l"(d)); \
    lo = __uint_as_float(_l); hi = __uint_as_float(_h); } while(0)

// ---------------- device scratch (no allocations allowed) ----------------
__device__ int   g_top[MAXN];          // packed top-2 expert ids per token
__device__ float g_conf[MAXN];         // top-1 logit per token
__device__ int   g_bcnt[NBMAX*Ek];     // per-block per-expert routed counts
__device__ int   g_boff[NBMAX*Ek];     // exclusive prefix of the above
__device__ float g_csum[NBMAX];        // per-block confidence partial sums
__device__ int   g_list[Ek*CAPSTRIDE]; // compacted kept-token lists
__device__ int   g_Me[Ek];             // kept count per expert (= load)

// ---------------- router: logits = x@Wr + br, top-2, confidence ----------
__global__ void router_kernel(const float* __restrict__ x,
                              const float* __restrict__ Wr,
                              const float* __restrict__ br, int N)
{
    __shared__ float sWr[Dk*Ek]; // 16 KB
    int t = threadIdx.x;
    for (int i = t; i < Dk*Ek/4; i += 256)
        ((float4*)sWr)[i] = ((const float4*)Wr)[i];
    __syncthreads();

    int tok  = blockIdx.x*8 + (t >> 5);   // one warp per token
    int lane = t & 31;
    if (tok >= N) return;
    const float* xr = x + (size_t)tok*Dk;

    float acc[Ek];
#pragma unroll
    for (int e = 0; e < Ek; e++) acc[e] = 0.f;

    for (int c = lane; c < Dk/4; c += 32) {
        float4 v = *(const float4*)(xr + c*4);
        const float* w = sWr + c*4*Ek;
        float xv[4] = {v.x, v.y, v.z, v.w};
#pragma unroll
        for (int kk = 0; kk < 4; kk++)
#pragma unroll
            for (int e = 0; e < Ek; e++)
                acc[e] = fmaf(xv[kk], w[kk*Ek + e], acc[e]);
    }
#pragma unroll
    for (int off = 16; off; off >>= 1)
#pragma unroll
        for (int e = 0; e < Ek; e++)
            acc[e] += __shfl_xor_sync(0xffffffffu, acc[e], off);

    if (lane == 0) {
        float v1 = -3e38f, v2 = -3e38f; int i1 = 0, i2 = 1;
#pragma unroll
        for (int e = 0; e < Ek; e++) {
            float v = acc[e] + br[e];
            if (v > v1)      { v2 = v1; i2 = i1; v1 = v; i1 = e; }  // strict > matches jax tie order
            else if (v > v2) { v2 = v;  i2 = e; }
        }
        g_top[tok]  = i1 | (i2 << 4);
        g_conf[tok] = v1;
    }
}

// ---------------- scan stage 1: per-block routed counts + conf partials --
__global__ void scan1_kernel(int N)
{
    __shared__ int   cnt[Ek];
    __shared__ float red[256];
    int t = threadIdx.x, b = blockIdx.x;
    if (t < Ek) cnt[t] = 0;
    __syncthreads();
    int n = b*256 + t;
    float c = 0.f;
    if (n < N) {
        int pk = g_top[n];
        atomicAdd(&cnt[pk & 15], 1);
        atomicAdd(&cnt[(pk >> 4) & 15], 1);
        c = g_conf[n];
    }
    red[t] = c; __syncthreads();
    for (int s = 128; s > 0; s >>= 1) { if (t < s) red[t] += red[t+s]; __syncthreads(); }
    if (t < Ek) g_bcnt[b*Ek + t] = cnt[t];
    if (t == 0) g_csum[b] = red[0];
}

// ---------------- scan stage 2: exclusive scan + load stats + tail out ---
__global__ void scan2_kernel(int NB, int N, int cap, float* tail)
{
    int e = threadIdx.x;
    __shared__ int totals[Ek];
    if (e < Ek) {
        int run = 0;
        for (int b = 0; b < NB; b++) { g_boff[b*Ek + e] = run; run += g_bcnt[b*Ek + e]; }
        totals[e] = run;
        g_Me[e] = run < cap ? run : cap;
    }
    __syncthreads();
    if (e == 0) {
        float s = 0.f, load[Ek];
        for (int i = 0; i < Ek; i++) {
            int l = totals[i] < cap ? totals[i] : cap;
            load[i] = (float)l; s += load[i];
        }
        float inv = 1.f / (s + 1e-8f);
        float loss = 0.f;
        for (int i = 0; i < Ek; i++) {
            float d = load[i] * inv;
            loss += d * logf(d + 1e-8f);
            tail[1 + i] = d;               // load_dist
        }
        tail[0] = loss;                    // load_loss
        float cs = 0.f;
        for (int b = 0; b < NB; b++) cs += g_csum[b];
        tail[9] = cs / (float)N;           // confidence
    }
}

// ---------------- scan stage 3: compacted kept-token lists (parallel) ----
// block = 256 threads; warp e handles expert e via ballot ranking
__global__ void scan3_kernel(int N, int cap)
{
    __shared__ int spk[256];
    int t = threadIdx.x, b = blockIdx.x;
    int base = b*256;
    int lim = N - base; if (lim > 256) lim = 256;
    spk[t] = (t < lim) ? g_top[base + t] : -1;
    __syncthreads();
    int e = t >> 5, lane = t & 31;
    int run = g_boff[b*Ek + e];
#pragma unroll
    for (int r = 0; r < 8; r++) {
        int i = r*32 + lane;
        int pk = spk[i];
        bool m = (pk >= 0) && (((pk & 15) == e) || (((pk >> 4) & 15) == e));
        unsigned bal = __ballot_sync(0xffffffffu, m);
        if (m) {
            int idx = run + __popc(bal & ((1u << lane) - 1u));
            if (idx < cap) g_list[e*CAPSTRIDE + idx] = base + i;
        }
        run += __popc(bal);
    }
}

// ---------------- fused per-expert FFN: out += relu(Xg W1 + b1) W2 + b2 --
// block = 256 threads (16x16), tile MT=64 x H=128, packed f32x2 FMA (FFMA2)
__global__ void __launch_bounds__(256)
ffn_kernel(const float* __restrict__ x,  const float* __restrict__ W1,
           const float* __restrict__ b1, const float* __restrict__ W2,
           const float* __restrict__ b2, float* __restrict__ out)
{
    constexpr int MT = 64, KT = 16, HS = 129;
    __shared__ float Xs[KT*MT];     //  4 KB (k-major)
    __shared__ float Ws[KT*Hk];     //  8 KB (shared by both GEMM phases)
    __shared__ float Hs[MT*HS];     // ~33 KB
    __shared__ int   rows[MT];

    int e  = blockIdx.y;
    int Me = g_Me[e];
    int m0 = blockIdx.x * MT;
    if (m0 >= Me) return;

    int tid = threadIdx.x;
    int tx = tid & 15, ty = tid >> 4;

    if (tid < MT) {
        int m = m0 + tid;
        rows[tid] = g_list[e*CAPSTRIDE + (m < Me ? m : (Me - 1))];
    }
    __syncthreads();

    // ---- phase 1: H[64,128] = Xg[64,512] @ W1[512,128] ----
    const float* W1e = W1 + (size_t)e*Dk*Hk;
    ull acc[4][4];
#pragma unroll
    for (int i = 0; i < 4; i++)
#pragma unroll
        for (int j = 0; j < 4; j++) acc[i][j] = 0ull;

    for (int k0 = 0; k0 < Dk; k0 += KT) {
        { // gather X tile -> Xs[k][m] (transposed)
            int m = tid >> 2, c4 = tid & 3;
            float4 v = *(const float4*)(x + (size_t)rows[m]*Dk + k0 + c4*4);
            Xs[(c4*4+0)*MT + m] = v.x; Xs[(c4*4+1)*MT + m] = v.y;
            Xs[(c4*4+2)*MT + m] = v.z; Xs[(c4*4+3)*MT + m] = v.w;
        }
#pragma unroll
        for (int r = 0; r < 2; r++) { // W1 tile -> Ws[k][h]
            int q = tid*2 + r; int k = q >> 5; int h = (q & 31)*4;
            *(float4*)&Ws[k*Hk + h] = *(const float4*)&W1e[(size_t)(k0+k)*Hk + h];
        }
        __syncthreads();
#pragma unroll
        for (int k = 0; k < KT; k++) {
            float4 av = *(const float4*)&Xs[k*MT + ty*4];
            ull ap0, ap1, ap2, ap3;
            PACK2(ap0, av.x); PACK2(ap1, av.y); PACK2(ap2, av.z); PACK2(ap3, av.w);
            ulonglong2 b01 = *(const ulonglong2*)&Ws[k*Hk + tx*8];
            ulonglong2 b23 = *(const ulonglong2*)&Ws[k*Hk + tx*8 + 4];
            FMA2(acc[0][0], ap0, b01.x); FMA2(acc[0][1], ap0, b01.y);
            FMA2(acc[0][2], ap0, b23.x); FMA2(acc[0][3], ap0, b23.y);
            FMA2(acc[1][0], ap1, b01.x); FMA2(acc[1][1], ap1, b01.y);
            FMA2(acc[1][2], ap1, b23.x); FMA2(acc[1][3], ap1, b23.y);
            FMA2(acc[2][0], ap2, b01.x); FMA2(acc[2][1], ap2, b01.y);
            FMA2(acc[2][2], ap2, b23.x); FMA2(acc[2][3], ap2, b23.y);
            FMA2(acc[3][0], ap3, b01.x); FMA2(acc[3][1], ap3, b01.y);
            FMA2(acc[3][2], ap3, b23.x); FMA2(acc[3][3], ap3, b23.y);
        }
        __syncthreads();
    }

    // ---- relu + b1 -> Hs[m][h] ----
    {
        const float* b1e = b1 + e*Hk;
        float bb[8];
#pragma unroll
        for (int j = 0; j < 8; j++) bb[j] = b1e[tx*8 + j];
#pragma unroll
        for (int i = 0; i < 4; i++)
#pragma unroll
            for (int jp = 0; jp < 4; jp++) {
                float lo, hi;
                UNPACK2(lo, hi, acc[i][jp]);
                Hs[(ty*4+i)*HS + tx*8 + jp*2]     = fmaxf(lo + bb[jp*2],   0.f);
                Hs[(ty*4+i)*HS + tx*8 + jp*2 + 1] = fmaxf(hi + bb[jp*2+1], 0.f);
            }
    }
    __syncthreads();

    // ---- phase 2: out[64,512] += H[64,128] @ W2[128,512] + b2 ----
    const float* W2e = W2 + (size_t)e*Hk*Dk;
    const float* b2e = b2 + (size_t)e*Dk;
    for (int n0 = 0; n0 < Dk; n0 += 128) {
        ull acc2[4][4];
#pragma unroll
        for (int i = 0; i < 4; i++)
#pragma unroll
            for (int j = 0; j < 4; j++) acc2[i][j] = 0ull;

        for (int k0 = 0; k0 < Hk; k0 += KT) {
#pragma unroll
            for (int r = 0; r < 2; r++) { // W2 chunk -> Ws[k][h]
                int q = tid*2 + r; int k = q >> 5; int h = (q & 31)*4;
                *(float4*)&Ws[k*Hk + h] = *(const float4*)&W2e[(size_t)(k0+k)*Dk + n0 + h];
            }
            __syncthreads();
#pragma unroll
            for (int k = 0; k < KT; k++) {
                ulonglong2 b01 = *(const ulonglong2*)&Ws[k*Hk + tx*8];
                ulonglong2 b23 = *(const ulonglong2*)&Ws[k*Hk + tx*8 + 4];
                ull hp0, hp1, hp2, hp3;
                PACK2(hp0, Hs[(ty*4+0)*HS + k0 + k]);
                PACK2(hp1, Hs[(ty*4+1)*HS + k0 + k]);
                PACK2(hp2, Hs[(ty*4+2)*HS + k0 + k]);
                PACK2(hp3, Hs[(ty*4+3)*HS + k0 + k]);
                FMA2(acc2[0][0], hp0, b01.x); FMA2(acc2[0][1], hp0, b01.y);
                FMA2(acc2[0][2], hp0, b23.x); FMA2(acc2[0][3], hp0, b23.y);
                FMA2(acc2[1][0], hp1, b01.x); FMA2(acc2[1][1], hp1, b01.y);
                FMA2(acc2[1][2], hp1, b23.x); FMA2(acc2[1][3], hp1, b23.y);
                FMA2(acc2[2][0], hp2, b01.x); FMA2(acc2[2][1], hp2, b01.y);
                FMA2(acc2[2][2], hp2, b23.x); FMA2(acc2[2][3], hp2, b23.y);
                FMA2(acc2[3][0], hp3, b01.x); FMA2(acc2[3][1], hp3, b01.y);
                FMA2(acc2[3][2], hp3, b23.x); FMA2(acc2[3][3], hp3, b23.y);
            }
            __syncthreads();
        }

        float b2r[8];
#pragma unroll
        for (int j = 0; j < 8; j++) b2r[j] = b2e[n0 + tx*8 + j];
#pragma unroll
        for (int i = 0; i < 4; i++) {
            if (m0 + ty*4 + i < Me) {
                float* op = out + (size_t)rows[ty*4+i]*Dk + n0 + tx*8;
#pragma unroll
                for (int jp = 0; jp < 4; jp++) {
                    float lo, hi;
                    UNPACK2(lo, hi, acc2[i][jp]);
                    atomicAdd(op + jp*2,     lo + b2r[jp*2]);
                    atomicAdd(op + jp*2 + 1, hi + b2r[jp*2+1]);
                }
            }
        }
    }
}

// ---------------- launch ----------------
extern "C" void kernel_launch(void* const* d_in, const int* in_sizes, int n_in,
                              void* d_out, int out_size)
{
    const float* x  = (const float*)d_in[0];
    const float* Wr = (const float*)d_in[1];
    const float* br = (const float*)d_in[2];
    const float* W1 = (const float*)d_in[3];
    const float* b1 = (const float*)d_in[4];
    const float* W2 = (const float*)d_in[5];
    const float* b2 = (const float*)d_in[6];
    float* out = (float*)d_out;

    int N = in_sizes[0] / Dk;
    if (N > MAXN) N = MAXN;
    int cap = (int)(1.25f * ((float)N / (float)Ek));
    if (cap > CAPSTRIDE) cap = CAPSTRIDE;
    int NB = (N + 255) / 256;

    cudaMemsetAsync(d_out, 0, (size_t)out_size * sizeof(float), 0);
    router_kernel<<<(N + 7) / 8, 256>>>(x, Wr, br, N);
    scan1_kernel<<<NB, 256>>>(N);
    scan2_kernel<<<1, Ek>>>(NB, N, cap, out + (size_t)N * Dk);
    scan3_kernel<<<NB, 256>>>(N, cap);

    int tiles = (cap + 63) / 64;
    dim3 grid(tiles, Ek);
    ffn_kernel<<<grid, 256>>>(x, W1, b1, W2, b2, out);
}

// round 3
// speedup vs baseline: 1.3629x; 1.3241x over previous
#include <cuda_runtime.h>
#include <math.h>

#define Dk 512
#define Ek 8
#define Hk 128
#define MAXN 32768
#define CAPSTRIDE 5120
#define NBMAX (MAXN/256)

typedef unsigned long long ull;

// pack a float into both halves of a 64-bit f32x2 register
#define PACK2(d, v) do { unsigned _u = __float_as_uint(v); \
    asm("mov.b64 %0, {%1, %2};" : "=l"(d) : "r"(_u), "r"(_u)); } while(0)
// d = a * b + d  (elementwise f32x2) — FFMA2 in SASS
#define FMA2(d, a, b) asm("fma.rn.f32x2 %0, %1, %2, %0;" : "+l"(d) : "l"(a), "l"(b))
#define UNPACK2(lo, hi, d) do { unsigned _l, _h; \
    asm("mov.b64 {%0, %1}, %2;" : "=r"(_l), "=r"(_h) : "l"(d)); \
    lo = __uint_as_float(_l); hi = __uint_as_float(_h); } while(0)

__device__ __forceinline__ void cp16(void* dst, const void* src) {
    unsigned d = (unsigned)__cvta_generic_to_shared(dst);
    asm volatile("cp.async.cg.shared.global [%0], [%1], 16;" :: "r"(d), "l"(src));
}
#define CP_COMMIT asm volatile("cp.async.commit_group;")
#define CP_WAIT0  asm volatile("cp.async.wait_group 0;")

// ---------------- device scratch ----------------
__device__ int   g_top[MAXN];
__device__ float g_conf[MAXN];
__device__ int   g_bcnt[NBMAX*Ek];
__device__ int   g_boff[NBMAX*Ek];
__device__ float g_csum[NBMAX];
__device__ int   g_list[Ek*CAPSTRIDE];
__device__ int   g_Me[Ek];
__device__ int   g_tile;

// ---------------- router ----------------
__global__ void router_kernel(const float* __restrict__ x,
                              const float* __restrict__ Wr,
                              const float* __restrict__ br, int N)
{
    __shared__ float sWr[Dk*Ek];
    int t = threadIdx.x;
    for (int i = t; i < Dk*Ek/4; i += 256)
        ((float4*)sWr)[i] = ((const float4*)Wr)[i];
    __syncthreads();

    int tok  = blockIdx.x*8 + (t >> 5);
    int lane = t & 31;
    if (tok >= N) return;
    const float* xr = x + (size_t)tok*Dk;

    float acc[Ek];
#pragma unroll
    for (int e = 0; e < Ek; e++) acc[e] = 0.f;

    for (int c = lane; c < Dk/4; c += 32) {
        float4 v = *(const float4*)(xr + c*4);
        const float* w = sWr + c*4*Ek;
        float xv[4] = {v.x, v.y, v.z, v.w};
#pragma unroll
        for (int kk = 0; kk < 4; kk++)
#pragma unroll
            for (int e = 0; e < Ek; e++)
                acc[e] = fmaf(xv[kk], w[kk*Ek + e], acc[e]);
    }
#pragma unroll
    for (int off = 16; off; off >>= 1)
#pragma unroll
        for (int e = 0; e < Ek; e++)
            acc[e] += __shfl_xor_sync(0xffffffffu, acc[e], off);

    if (lane == 0) {
        float v1 = -3e38f, v2 = -3e38f; int i1 = 0, i2 = 1;
#pragma unroll
        for (int e = 0; e < Ek; e++) {
            float v = acc[e] + br[e];
            if (v > v1)      { v2 = v1; i2 = i1; v1 = v; i1 = e; }
            else if (v > v2) { v2 = v;  i2 = e; }
        }
        g_top[tok]  = i1 | (i2 << 4);
        g_conf[tok] = v1;
    }
}

// ---------------- scan1: per-block routed counts + conf partials --------
__global__ void scan1_kernel(int N)
{
    __shared__ int   cnt[Ek];
    __shared__ float red[256];
    int t = threadIdx.x, b = blockIdx.x;
    if (t < Ek) cnt[t] = 0;
    __syncthreads();
    int n = b*256 + t;
    float c = 0.f;
    if (n < N) {
        int pk = g_top[n];
        atomicAdd(&cnt[pk & 15], 1);
        atomicAdd(&cnt[(pk >> 4) & 15], 1);
        c = g_conf[n];
    }
    red[t] = c; __syncthreads();
    for (int s = 128; s > 0; s >>= 1) { if (t < s) red[t] += red[t+s]; __syncthreads(); }
    if (t < Ek) g_bcnt[b*Ek + t] = cnt[t];
    if (t == 0) g_csum[b] = red[0];
}

// ---------------- scan2: scan in smem (parallel load), stats, reset -----
__global__ void scan2_kernel(int NB, int N, int cap, float* tail)
{
    __shared__ int   sb[NBMAX*Ek];
    __shared__ float sc[NBMAX];
    __shared__ int   tot[Ek];
    int t = threadIdx.x;
    for (int i = t; i < NB*Ek; i += 256) sb[i] = g_bcnt[i];
    for (int i = t; i < NB;    i += 256) sc[i] = g_csum[i];
    if (t == 0) g_tile = 0;
    __syncthreads();
    if (t < Ek) {
        int run = 0;
        for (int b = 0; b < NB; b++) { g_boff[b*Ek + t] = run; run += sb[b*Ek + t]; }
        tot[t] = run;
        g_Me[t] = run < cap ? run : cap;
    }
    __syncthreads();
    if (t == 0) {
        float s = 0.f, load[Ek];
        for (int i = 0; i < Ek; i++) {
            int l = tot[i] < cap ? tot[i] : cap;
            load[i] = (float)l; s += load[i];
        }
        float inv = 1.f / (s + 1e-8f);
        float loss = 0.f;
        for (int i = 0; i < Ek; i++) {
            float d = load[i] * inv;
            loss += d * logf(d + 1e-8f);
            tail[1 + i] = d;
        }
        tail[0] = loss;
        float cs = 0.f;
        for (int b = 0; b < NB; b++) cs += sc[b];
        tail[9] = cs / (float)N;
    }
}

// ---------------- scan3: compacted kept-token lists (ballot rank) -------
__global__ void scan3_kernel(int N, int cap)
{
    __shared__ int spk[256];
    int t = threadIdx.x, b = blockIdx.x;
    int base = b*256;
    int lim = N - base; if (lim > 256) lim = 256;
    spk[t] = (t < lim) ? g_top[base + t] : -1;
    __syncthreads();
    int e = t >> 5, lane = t & 31;
    int run = g_boff[b*Ek + e];
#pragma unroll
    for (int r = 0; r < 8; r++) {
        int i = r*32 + lane;
        int pk = spk[i];
        bool m = (pk >= 0) && (((pk & 15) == e) || (((pk >> 4) & 15) == e));
        unsigned bal = __ballot_sync(0xffffffffu, m);
        if (m) {
            int idx = run + __popc(bal & ((1u << lane) - 1u));
            if (idx < cap) g_list[e*CAPSTRIDE + idx] = base + i;
        }
        run += __popc(bal);
    }
}

// ---------------- persistent fused FFN ----------------
// block = 128 threads (16 tx x 8 ty), tile MT=64 tokens x 128 cols,
// 8x8 per-thread register tile, FFMA2, cp.async double-buffered W tiles.
#define MT 64
#define NT 128
#define KT 16
#define HPAD 132
#define XS_OFF   0                      // 2*16*64*4  = 8192
#define WS_OFF   8192                   // 2*16*128*4 = 16384
#define HS_OFF   24576                  // 64*132*4   = 33792
#define ROWS_OFF 58368                  // 64*4
#define SMEM_BYTES 58624

__global__ void __launch_bounds__(128, 3)
ffn_kernel(const float* __restrict__ x,  const float* __restrict__ W1,
           const float* __restrict__ b1, const float* __restrict__ W2,
           const float* __restrict__ b2, float* __restrict__ out,
           int ntiles, int tilesPerE)
{
    extern __shared__ char smem[];
    float* Xs   = (float*)(smem + XS_OFF);   // [2][KT][MT]
    float* Ws   = (float*)(smem + WS_OFF);   // [2][KT][NT]
    float* Hs   = (float*)(smem + HS_OFF);   // [MT][HPAD]
    int*   rows = (int*)(smem + ROWS_OFF);
    __shared__ int s_tile;

#define XSm(buf,k,m) Xs[((buf)*KT + (k))*MT + (m)]
#define WSm(buf,k,n) Ws[((buf)*KT + (k))*NT + (n)]
#define HSm(m,k)     Hs[(m)*HPAD + (k)]

    int tid = threadIdx.x;
    int tx = tid & 15, ty = tid >> 4;       // tx: 0..15 (cols), ty: 0..7 (rows)
    int r  = tid >> 1, cA = (tid & 1)*8;    // X-gather assignment

    for (;;) {
        __syncthreads();
        if (tid == 0) s_tile = atomicAdd(&g_tile, 1);
        __syncthreads();
        int t = s_tile;
        if (t >= ntiles) return;
        int e  = t / tilesPerE;
        int m0 = (t - e*tilesPerE) * MT;
        int Me = g_Me[e];
        if (m0 >= Me) continue;

        if (tid < MT) {
            int m = m0 + tid;
            rows[tid] = g_list[e*CAPSTRIDE + (m < Me ? m : (Me - 1))];
        }
        __syncthreads();

        const float* W1e = W1 + (size_t)e*Dk*Hk;
        const float* W2e = W2 + (size_t)e*Hk*Dk;
        const size_t xrow = (size_t)rows[r]*Dk + cA;

        // ================= phase 1: H = relu(Xg @ W1 + b1) =================
        // prologue: stage 0 into buf 0
        {
            float4 av0 = *(const float4*)(x + xrow);
            float4 av1 = *(const float4*)(x + xrow + 4);
#pragma unroll
            for (int q4 = 0; q4 < 4; q4++) {
                int q = tid*4 + q4; int k = q >> 5; int c = q & 31;
                cp16(&WSm(0,k,c*4), W1e + (size_t)k*Hk + c*4);
            }
            CP_COMMIT;
            XSm(0,cA+0,r)=av0.x; XSm(0,cA+1,r)=av0.y; XSm(0,cA+2,r)=av0.z; XSm(0,cA+3,r)=av0.w;
            XSm(0,cA+4,r)=av1.x; XSm(0,cA+5,r)=av1.y; XSm(0,cA+6,r)=av1.z; XSm(0,cA+7,r)=av1.w;
            CP_WAIT0; __syncthreads();
        }

        ull acc[8][4];
#pragma unroll
        for (int i = 0; i < 8; i++)
#pragma unroll
            for (int j = 0; j < 4; j++) acc[i][j] = 0ull;

        for (int s = 0; s < Dk/KT; s++) {
            int cur = s & 1, nb = 1 - cur;
            bool more = (s + 1 < Dk/KT);
            float4 av0, av1;
            if (more) {
                const float* ap = x + xrow + (s+1)*KT;
                av0 = *(const float4*)ap; av1 = *(const float4*)(ap + 4);
#pragma unroll
                for (int q4 = 0; q4 < 4; q4++) {
                    int q = tid*4 + q4; int k = q >> 5; int c = q & 31;
                    cp16(&WSm(nb,k,c*4), W1e + (size_t)((s+1)*KT + k)*Hk + c*4);
                }
            }
            CP_COMMIT;
#pragma unroll
            for (int k = 0; k < KT; k++) {
                float4 a0 = *(const float4*)&XSm(cur,k,ty*8);
                float4 a1 = *(const float4*)&XSm(cur,k,ty*8+4);
                ull ap0,ap1,ap2,ap3,ap4,ap5,ap6,ap7;
                PACK2(ap0,a0.x); PACK2(ap1,a0.y); PACK2(ap2,a0.z); PACK2(ap3,a0.w);
                PACK2(ap4,a1.x); PACK2(ap5,a1.y); PACK2(ap6,a1.z); PACK2(ap7,a1.w);
                ulonglong2 b01 = *(const ulonglong2*)&WSm(cur,k,tx*8);
                ulonglong2 b23 = *(const ulonglong2*)&WSm(cur,k,tx*8+4);
                FMA2(acc[0][0],ap0,b01.x); FMA2(acc[0][1],ap0,b01.y); FMA2(acc[0][2],ap0,b23.x); FMA2(acc[0][3],ap0,b23.y);
                FMA2(acc[1][0],ap1,b01.x); FMA2(acc[1][1],ap1,b01.y); FMA2(acc[1][2],ap1,b23.x); FMA2(acc[1][3],ap1,b23.y);
                FMA2(acc[2][0],ap2,b01.x); FMA2(acc[2][1],ap2,b01.y); FMA2(acc[2][2],ap2,b23.x); FMA2(acc[2][3],ap2,b23.y);
                FMA2(acc[3][0],ap3,b01.x); FMA2(acc[3][1],ap3,b01.y); FMA2(acc[3][2],ap3,b23.x); FMA2(acc[3][3],ap3,b23.y);
                FMA2(acc[4][0],ap4,b01.x); FMA2(acc[4][1],ap4,b01.y); FMA2(acc[4][2],ap4,b23.x); FMA2(acc[4][3],ap4,b23.y);
                FMA2(acc[5][0],ap5,b01.x); FMA2(acc[5][1],ap5,b01.y); FMA2(acc[5][2],ap5,b23.x); FMA2(acc[5][3],ap5,b23.y);
                FMA2(acc[6][0],ap6,b01.x); FMA2(acc[6][1],ap6,b01.y); FMA2(acc[6][2],ap6,b23.x); FMA2(acc[6][3],ap6,b23.y);
                FMA2(acc[7][0],ap7,b01.x); FMA2(acc[7][1],ap7,b01.y); FMA2(acc[7][2],ap7,b23.x); FMA2(acc[7][3],ap7,b23.y);
            }
            if (more) {
                XSm(nb,cA+0,r)=av0.x; XSm(nb,cA+1,r)=av0.y; XSm(nb,cA+2,r)=av0.z; XSm(nb,cA+3,r)=av0.w;
                XSm(nb,cA+4,r)=av1.x; XSm(nb,cA+5,r)=av1.y; XSm(nb,cA+6,r)=av1.z; XSm(nb,cA+7,r)=av1.w;
            }
            CP_WAIT0; __syncthreads();
        }

        // relu + b1 -> Hs[m][h]
        {
            const float* b1e = b1 + e*Hk;
            float bb[8];
#pragma unroll
            for (int j = 0; j < 8; j++) bb[j] = b1e[tx*8 + j];
#pragma unroll
            for (int i = 0; i < 8; i++) {
                float o[8];
#pragma unroll
                for (int jp = 0; jp < 4; jp++) UNPACK2(o[2*jp], o[2*jp+1], acc[i][jp]);
#pragma unroll
                for (int j = 0; j < 8; j++) o[j] = fmaxf(o[j] + bb[j], 0.f);
                *(float4*)&HSm(ty*8+i, tx*8)   = make_float4(o[0],o[1],o[2],o[3]);
                *(float4*)&HSm(ty*8+i, tx*8+4) = make_float4(o[4],o[5],o[6],o[7]);
            }
        }

        // ================= phase 2: out += H @ W2 + b2 =================
        {
#pragma unroll
            for (int q4 = 0; q4 < 4; q4++) {
                int q = tid*4 + q4; int k = q >> 5; int c = q & 31;
                cp16(&WSm(0,k,c*4), W2e + (size_t)k*Dk + c*4);
            }
            CP_COMMIT; CP_WAIT0; __syncthreads();  // also publishes Hs
        }

        ull acc2[8][4];
        for (int ss = 0; ss < 32; ss++) {
            int cur = ss & 1, nb = 1 - cur;
            int n0 = ss >> 3, k0 = ss & 7;
            if (k0 == 0) {
#pragma unroll
                for (int i = 0; i < 8; i++)
#pragma unroll
                    for (int j = 0; j < 4; j++) acc2[i][j] = 0ull;
            }
            if (ss + 1 < 32) {
                int nn0 = (ss+1) >> 3, nk0 = (ss+1) & 7;
#pragma unroll
                for (int q4 = 0; q4 < 4; q4++) {
                    int q = tid*4 + q4; int k = q >> 5; int c = q & 31;
                    cp16(&WSm(nb,k,c*4), W2e + (size_t)(nk0*KT + k)*Dk + nn0*NT + c*4);
                }
            }
            CP_COMMIT;
#pragma unroll
            for (int k = 0; k < KT; k++) {
                int kk = k0*KT + k;
                ull hp0,hp1,hp2,hp3,hp4,hp5,hp6,hp7;
                PACK2(hp0, HSm(ty*8+0, kk)); PACK2(hp1, HSm(ty*8+1, kk));
                PACK2(hp2, HSm(ty*8+2, kk)); PACK2(hp3, HSm(ty*8+3, kk));
                PACK2(hp4, HSm(ty*8+4, kk)); PACK2(hp5, HSm(ty*8+5, kk));
                PACK2(hp6, HSm(ty*8+6, kk)); PACK2(hp7, HSm(ty*8+7, kk));
                ulonglong2 b01 = *(const ulonglong2*)&WSm(cur,k,tx*8);
                ulonglong2 b23 = *(const ulonglong2*)&WSm(cur,k,tx*8+4);
                FMA2(acc2[0][0],hp0,b01.x); FMA2(acc2[0][1],hp0,b01.y); FMA2(acc2[0][2],hp0,b23.x); FMA2(acc2[0][3],hp0,b23.y);
                FMA2(acc2[1][0],hp1,b01.x); FMA2(acc2[1][1],hp1,b01.y); FMA2(acc2[1][2],hp1,b23.x); FMA2(acc2[1][3],hp1,b23.y);
                FMA2(acc2[2][0],hp2,b01.x); FMA2(acc2[2][1],hp2,b01.y); FMA2(acc2[2][2],hp2,b23.x); FMA2(acc2[2][3],hp2,b23.y);
                FMA2(acc2[3][0],hp3,b01.x); FMA2(acc2[3][1],hp3,b01.y); FMA2(acc2[3][2],hp3,b23.x); FMA2(acc2[3][3],hp3,b23.y);
                FMA2(acc2[4][0],hp4,b01.x); FMA2(acc2[4][1],hp4,b01.y); FMA2(acc2[4][2],hp4,b23.x); FMA2(acc2[4][3],hp4,b23.y);
                FMA2(acc2[5][0],hp5,b01.x); FMA2(acc2[5][1],hp5,b01.y); FMA2(acc2[5][2],hp5,b23.x); FMA2(acc2[5][3],hp5,b23.y);
                FMA2(acc2[6][0],hp6,b01.x); FMA2(acc2[6][1],hp6,b01.y); FMA2(acc2[6][2],hp6,b23.x); FMA2(acc2[6][3],hp6,b23.y);
                FMA2(acc2[7][0],hp7,b01.x); FMA2(acc2[7][1],hp7,b01.y); FMA2(acc2[7][2],hp7,b23.x); FMA2(acc2[7][3],hp7,b23.y);
            }
            CP_WAIT0; __syncthreads();

            if (k0 == 7) {
                const float* b2e = b2 + (size_t)e*Dk + n0*NT;
                float b2r[8];
#pragma unroll
                for (int j = 0; j < 8; j++) b2r[j] = b2e[tx*8 + j];
#pragma unroll
                for (int i = 0; i < 8; i++) {
                    if (m0 + ty*8 + i < Me) {
                        float* op = out + (size_t)rows[ty*8+i]*Dk + n0*NT + tx*8;
#pragma unroll
                        for (int jp = 0; jp < 4; jp++) {
                            float lo, hi;
                            UNPACK2(lo, hi, acc2[i][jp]);
                            atomicAdd(op + 2*jp,     lo + b2r[2*jp]);
                            atomicAdd(op + 2*jp + 1, hi + b2r[2*jp+1]);
                        }
                    }
                }
            }
        }
    }
#undef XSm
#undef WSm
#undef HSm
}

// ---------------- launch ----------------
extern "C" void kernel_launch(void* const* d_in, const int* in_sizes, int n_in,
                              void* d_out, int out_size)
{
    const float* x  = (const float*)d_in[0];
    const float* Wr = (const float*)d_in[1];
    const float* br = (const float*)d_in[2];
    const float* W1 = (const float*)d_in[3];
    const float* b1 = (const float*)d_in[4];
    const float* W2 = (const float*)d_in[5];
    const float* b2 = (const float*)d_in[6];
    float* out = (float*)d_out;

    int N = in_sizes[0] / Dk;
    if (N > MAXN) N = MAXN;
    int cap = (int)(1.25f * ((float)N / (float)Ek));
    if (cap > CAPSTRIDE) cap = CAPSTRIDE;
    int NB = (N + 255) / 256;

    static int smem_set = 0;
    if (!smem_set) {
        cudaFuncSetAttribute(ffn_kernel, cudaFuncAttributeMaxDynamicSharedMemorySize, SMEM_BYTES);
        smem_set = 1;
    }

    cudaMemsetAsync(d_out, 0, (size_t)out_size * sizeof(float), 0);
    router_kernel<<<(N + 7) / 8, 256>>>(x, Wr, br, N);
    scan1_kernel<<<NB, 256>>>(N);
    scan2_kernel<<<1, 256>>>(NB, N, cap, out + (size_t)N * Dk);
    scan3_kernel<<<NB, 256>>>(N, cap);

    int tilesPerE = (cap + MT - 1) / MT;
    int ntiles = tilesPerE * Ek;
    ffn_kernel<<<148*3, 128, SMEM_BYTES>>>(x, W1, b1, W2, b2, out, ntiles, tilesPerE);
}